// round 1
// baseline (speedup 1.0000x reference)
#include <cuda_runtime.h>
#include <math.h>

// ---------------- problem constants ----------------
#define BVAL 32
#define CCH 3
#define HH 224
#define WW 224
#define PS 16
#define DIM 768
#define NHEAD 12
#define HDIM 64
#define DEPTH 12
#define MLPD 3072
#define NCLS 1000
#define GH_ 14
#define GW_ 14
#define TT 196
#define PD 768               // patch dim = 16*16*3
#define MTOK (BVAL*TT)       // 6272 token rows

// ---------------- scratch (device globals; no runtime alloc allowed) ----------------
__device__ float g_P  [MTOK*PD];
__device__ float g_h  [MTOK*DIM];
__device__ float g_xn [MTOK*DIM];
__device__ float g_q  [MTOK*DIM];
__device__ float g_k  [MTOK*DIM];
__device__ float g_v  [MTOK*DIM];
__device__ float g_att[MTOK*DIM];
__device__ float g_S  [BVAL*NHEAD*TT*TT];
__device__ float g_m1 [(size_t)MTOK*MLPD];
__device__ float g_pos[TT*DIM];
__device__ float g_Wq [DEPTH*DIM*DIM];
__device__ float g_Wk [DEPTH*DIM*DIM];
__device__ float g_Wv [DEPTH*DIM*DIM];
__device__ float g_pool[BVAL*DIM];

// ---------------- small kernels ----------------

// patchify: P[b*T+t][(p1*16+p2)*3+c] = x[b][c][gh*16+p1][gw*16+p2]
__global__ void patchify_k(const float* __restrict__ x, float* __restrict__ P) {
    int idx = blockIdx.x * blockDim.x + threadIdx.x;
    if (idx >= MTOK * PD) return;
    int bt = idx / PD, pc = idx % PD;
    int c = pc % 3, p2 = (pc / 3) % 16, p1 = pc / 48;
    int b = bt / TT, t = bt % TT;
    int gh = t / GW_, gw = t % GW_;
    P[idx] = x[((b * CCH + c) * HH + gh * PS + p1) * WW + gw * PS + p2];
}

// pack W[l][h][d][e] -> out[l][d][h*64+e]  (so projection is a plain [768,768] GEMM)
__global__ void pack_qkv_k(const float* __restrict__ W, float* __restrict__ out) {
    int idx = blockIdx.x * blockDim.x + threadIdx.x;
    if (idx >= DEPTH * DIM * DIM) return;
    int l = idx / (DIM * DIM);
    int r = idx % (DIM * DIM);
    int d = r / DIM, n = r % DIM;
    int h = n / HDIM, e = n % HDIM;
    out[idx] = W[((l * NHEAD + h) * DIM + d) * HDIM + e];
}

// sincos 2D posemb [T, D]
__global__ void pos_k(float* __restrict__ pos) {
    int idx = blockIdx.x * blockDim.x + threadIdx.x;
    if (idx >= TT * DIM) return;
    int t = idx / DIM, d = idx % DIM;
    int q = d / 192, j = d % 192;
    float omega = powf(10000.0f, -(float)j / 191.0f);
    float yv = (float)(t / GW_) * omega;
    float xv = (float)(t % GW_) * omega;
    float v = (q == 0) ? sinf(xv) : (q == 1) ? cosf(xv) : (q == 2) ? sinf(yv) : cosf(yv);
    pos[idx] = v;
}

__global__ void addpos_k(float* __restrict__ h, const float* __restrict__ pos) {
    int idx = blockIdx.x * blockDim.x + threadIdx.x;
    if (idx >= MTOK * DIM) return;
    int bt = idx / DIM, d = idx % DIM;
    int t = bt % TT;
    h[idx] += pos[t * DIM + d];
}

// LayerNorm over D=768; one block (256 thr) per row
__global__ void ln_k(const float* __restrict__ X, const float* __restrict__ g,
                     const float* __restrict__ b, float* __restrict__ Y) {
    int row = blockIdx.x;
    int tid = threadIdx.x;
    const float* xr = X + (size_t)row * DIM;
    float v[3], s = 0.f, s2 = 0.f;
#pragma unroll
    for (int i = 0; i < 3; i++) {
        v[i] = xr[tid + i * 256];
        s += v[i];
        s2 += v[i] * v[i];
    }
#pragma unroll
    for (int o = 16; o; o >>= 1) {
        s  += __shfl_xor_sync(0xffffffffu, s,  o);
        s2 += __shfl_xor_sync(0xffffffffu, s2, o);
    }
    __shared__ float sm[8], sm2[8];
    __shared__ float mu_s, rstd_s;
    int w = tid >> 5, lane = tid & 31;
    if (!lane) { sm[w] = s; sm2[w] = s2; }
    __syncthreads();
    if (tid == 0) {
        float a = 0.f, a2 = 0.f;
        for (int i = 0; i < 8; i++) { a += sm[i]; a2 += sm2[i]; }
        float mu = a / 768.0f;
        float var = a2 / 768.0f - mu * mu;
        mu_s = mu;
        rstd_s = rsqrtf(var + 1e-5f);
    }
    __syncthreads();
    float mu = mu_s, rstd = rstd_s;
#pragma unroll
    for (int i = 0; i < 3; i++) {
        int d = tid + i * 256;
        Y[(size_t)row * DIM + d] = (v[i] - mu) * rstd * g[d] + b[d];
    }
}

// ---------------- 128x128x8 SGEMM, templated epilogue ----------------
// EPI 0: C = acc (+bias)           EPI 1: C = acc + bias + R       EPI 2: C = gelu(acc + bias)
// Requires M%128==0, N%128==0, K%8==0 (true for all uses here).
template <int EPI>
__global__ void __launch_bounds__(256)
sgemm_k(const float* __restrict__ A, const float* __restrict__ B,
        const float* __restrict__ bias, const float* __restrict__ R,
        float* __restrict__ C, int M, int N, int K) {
    __shared__ float As[8][128];
    __shared__ float Bs[8][128];
    int tid = threadIdx.x;
    int bx = blockIdx.x, by = blockIdx.y;
    const float* Ab = A + (size_t)by * 128 * K;
    const float* Bb = B + (size_t)bx * 128;
    int a_r = tid >> 1, a_c = (tid & 1) << 2;
    int b_r = tid >> 5, b_c = (tid & 31) << 2;
    int tx = tid & 15, ty = tid >> 4;
    float acc[8][8];
#pragma unroll
    for (int i = 0; i < 8; i++)
#pragma unroll
        for (int j = 0; j < 8; j++) acc[i][j] = 0.f;

    for (int k0 = 0; k0 < K; k0 += 8) {
        float4 av = *(const float4*)(Ab + (size_t)a_r * K + k0 + a_c);
        As[a_c + 0][a_r] = av.x;
        As[a_c + 1][a_r] = av.y;
        As[a_c + 2][a_r] = av.z;
        As[a_c + 3][a_r] = av.w;
        *(float4*)(&Bs[b_r][b_c]) = *(const float4*)(Bb + (size_t)(k0 + b_r) * N + b_c);
        __syncthreads();
#pragma unroll
        for (int kk = 0; kk < 8; kk++) {
            float4 a0 = *(const float4*)&As[kk][ty * 4];
            float4 a1 = *(const float4*)&As[kk][64 + ty * 4];
            float4 b0 = *(const float4*)&Bs[kk][tx * 4];
            float4 b1 = *(const float4*)&Bs[kk][64 + tx * 4];
            float af[8] = {a0.x, a0.y, a0.z, a0.w, a1.x, a1.y, a1.z, a1.w};
            float bf[8] = {b0.x, b0.y, b0.z, b0.w, b1.x, b1.y, b1.z, b1.w};
#pragma unroll
            for (int i = 0; i < 8; i++)
#pragma unroll
                for (int j = 0; j < 8; j++) acc[i][j] += af[i] * bf[j];
        }
        __syncthreads();
    }
#pragma unroll
    for (int i = 0; i < 8; i++) {
        int row = by * 128 + ((i < 4) ? ty * 4 + i : 64 + ty * 4 + i - 4);
#pragma unroll
        for (int j = 0; j < 8; j++) {
            int col = bx * 128 + ((j < 4) ? tx * 4 + j : 64 + tx * 4 + j - 4);
            float vv = acc[i][j];
            if (bias) vv += bias[col];
            if (EPI == 1) vv += R[(size_t)row * N + col];
            if (EPI == 2) vv = 0.5f * vv * (1.0f + erff(vv * 0.70710678118654752f));
            C[(size_t)row * N + col] = vv;
        }
    }
}

// ---------------- attention ----------------
// scores + softmax: one block per (b*h, t); 224 threads (7 warps), thread s computes one score
__global__ void attn_scores_k(const float* __restrict__ Q, const float* __restrict__ K,
                              float* __restrict__ S) {
    int bh = blockIdx.x;    // 0..383
    int t = blockIdx.y;     // 0..195
    int b = bh / NHEAD, h = bh % NHEAD;
    int tid = threadIdx.x;  // 224
    int w = tid >> 5, lane = tid & 31;

    __shared__ float qsh[HDIM];
    __shared__ float sred[7];
    __shared__ float sbro;

    if (tid < HDIM) qsh[tid] = Q[(size_t)(b * TT + t) * DIM + h * HDIM + tid];
    __syncthreads();

    int s = tid;
    float val = -INFINITY;
    if (s < TT) {
        const float* kr = K + (size_t)(b * TT + s) * DIM + h * HDIM;
        float dot = 0.f;
#pragma unroll
        for (int d = 0; d < HDIM; d++) dot += qsh[d] * kr[d];
        val = dot * 0.125f;  // HD^-0.5
    }
    // block max
    float m = val;
#pragma unroll
    for (int o = 16; o; o >>= 1) m = fmaxf(m, __shfl_xor_sync(0xffffffffu, m, o));
    if (!lane) sred[w] = m;
    __syncthreads();
    if (tid == 0) {
        float mm = sred[0];
        for (int i = 1; i < 7; i++) mm = fmaxf(mm, sred[i]);
        sbro = mm;
    }
    __syncthreads();
    float rowmax = sbro;
    float e = (s < TT) ? expf(val - rowmax) : 0.f;
    // block sum
    float su = e;
#pragma unroll
    for (int o = 16; o; o >>= 1) su += __shfl_xor_sync(0xffffffffu, su, o);
    __syncthreads();
    if (!lane) sred[w] = su;
    __syncthreads();
    if (tid == 0) {
        float ss = 0.f;
        for (int i = 0; i < 7; i++) ss += sred[i];
        sbro = 1.0f / ss;
    }
    __syncthreads();
    if (s < TT) S[((size_t)bh * TT + t) * TT + s] = e * sbro;
}

// att = S @ V : one block per (b*h, t), 64 threads (one per e)
__global__ void attn_av_k(const float* __restrict__ S, const float* __restrict__ V,
                          float* __restrict__ O) {
    int bh = blockIdx.x, t = blockIdx.y;
    int b = bh / NHEAD, h = bh % NHEAD;
    int tid = threadIdx.x;  // 64
    __shared__ float psh[TT];
    for (int s = tid; s < TT; s += 64) psh[s] = S[((size_t)bh * TT + t) * TT + s];
    __syncthreads();
    float acc = 0.f;
    const float* vb = V + (size_t)b * TT * DIM + h * HDIM + tid;
#pragma unroll 4
    for (int s = 0; s < TT; s++) acc += psh[s] * vb[(size_t)s * DIM];
    O[(size_t)(b * TT + t) * DIM + h * HDIM + tid] = acc;
}

// ---------------- pool + head ----------------
__global__ void pool_k(const float* __restrict__ h, float* __restrict__ pool) {
    int idx = blockIdx.x * blockDim.x + threadIdx.x;
    if (idx >= BVAL * DIM) return;
    int b = idx / DIM, d = idx % DIM;
    float s = 0.f;
    const float* hp = h + (size_t)b * TT * DIM + d;
    for (int t = 0; t < TT; t++) s += hp[(size_t)t * DIM];
    pool[idx] = s * (1.0f / 196.0f);
}

__global__ void head_k(const float* __restrict__ pool, const float* __restrict__ W,
                       float* __restrict__ out) {
    int b = blockIdx.x;
    int tid = threadIdx.x;  // 256
    __shared__ float pr[DIM];
    for (int i = tid; i < DIM; i += 256) pr[i] = pool[b * DIM + i];
    __syncthreads();
    for (int n = tid; n < NCLS; n += 256) {
        float acc = 0.f;
        for (int k = 0; k < DIM; k++) acc += pr[k] * W[(size_t)k * NCLS + n];
        out[b * NCLS + n] = acc;
    }
}

// ---------------- launch ----------------
extern "C" void kernel_launch(void* const* d_in, const int* in_sizes, int n_in,
                              void* d_out, int out_size) {
    const float* x       = (const float*)d_in[0];
    const float* embed_W = (const float*)d_in[1];
    const float* embed_b = (const float*)d_in[2];
    const float* Wq      = (const float*)d_in[3];
    const float* Wk      = (const float*)d_in[4];
    const float* Wv      = (const float*)d_in[5];
    const float* Wo      = (const float*)d_in[6];
    const float* bo      = (const float*)d_in[7];
    const float* ln1_g   = (const float*)d_in[8];
    const float* ln1_b   = (const float*)d_in[9];
    const float* ln2_g   = (const float*)d_in[10];
    const float* ln2_b   = (const float*)d_in[11];
    const float* W1      = (const float*)d_in[12];
    const float* b1      = (const float*)d_in[13];
    const float* W2      = (const float*)d_in[14];
    const float* b2      = (const float*)d_in[15];
    const float* head_W  = (const float*)d_in[16];
    float* out = (float*)d_out;

    float *P, *h, *xn, *q, *k, *v, *att, *S, *m1, *pos, *wqp, *wkp, *wvp, *pool;
    cudaGetSymbolAddress((void**)&P,   g_P);
    cudaGetSymbolAddress((void**)&h,   g_h);
    cudaGetSymbolAddress((void**)&xn,  g_xn);
    cudaGetSymbolAddress((void**)&q,   g_q);
    cudaGetSymbolAddress((void**)&k,   g_k);
    cudaGetSymbolAddress((void**)&v,   g_v);
    cudaGetSymbolAddress((void**)&att, g_att);
    cudaGetSymbolAddress((void**)&S,   g_S);
    cudaGetSymbolAddress((void**)&m1,  g_m1);
    cudaGetSymbolAddress((void**)&pos, g_pos);
    cudaGetSymbolAddress((void**)&wqp, g_Wq);
    cudaGetSymbolAddress((void**)&wkp, g_Wk);
    cudaGetSymbolAddress((void**)&wvp, g_Wv);
    cudaGetSymbolAddress((void**)&pool, g_pool);

    patchify_k<<<(MTOK * PD + 255) / 256, 256>>>(x, P);
    pack_qkv_k<<<(DEPTH * DIM * DIM + 255) / 256, 256>>>(Wq, wqp);
    pack_qkv_k<<<(DEPTH * DIM * DIM + 255) / 256, 256>>>(Wk, wkp);
    pack_qkv_k<<<(DEPTH * DIM * DIM + 255) / 256, 256>>>(Wv, wvp);
    pos_k<<<(TT * DIM + 255) / 256, 256>>>(pos);

    // h = patches @ embed_W + embed_b ; then += posemb
    sgemm_k<0><<<dim3(DIM / 128, MTOK / 128), 256>>>(P, embed_W, embed_b, nullptr, h,
                                                     MTOK, DIM, PD);
    addpos_k<<<(MTOK * DIM + 255) / 256, 256>>>(h, pos);

    dim3 gproj(DIM / 128, MTOK / 128);     // 6 x 49
    dim3 gmlp1(MLPD / 128, MTOK / 128);    // 24 x 49
    dim3 gattn(BVAL * NHEAD, TT);          // 384 x 196

    for (int l = 0; l < DEPTH; l++) {
        ln_k<<<MTOK, 256>>>(h, ln1_g + l * DIM, ln1_b + l * DIM, xn);
        sgemm_k<0><<<gproj, 256>>>(xn, wqp + (size_t)l * DIM * DIM, nullptr, nullptr, q, MTOK, DIM, DIM);
        sgemm_k<0><<<gproj, 256>>>(xn, wkp + (size_t)l * DIM * DIM, nullptr, nullptr, k, MTOK, DIM, DIM);
        sgemm_k<0><<<gproj, 256>>>(xn, wvp + (size_t)l * DIM * DIM, nullptr, nullptr, v, MTOK, DIM, DIM);
        attn_scores_k<<<gattn, 224>>>(q, k, S);
        attn_av_k<<<gattn, 64>>>(S, v, att);
        sgemm_k<1><<<gproj, 256>>>(att, Wo + (size_t)l * DIM * DIM, bo + l * DIM, h, h, MTOK, DIM, DIM);
        ln_k<<<MTOK, 256>>>(h, ln2_g + l * DIM, ln2_b + l * DIM, xn);
        sgemm_k<2><<<gmlp1, 256>>>(xn, W1 + (size_t)l * DIM * MLPD, b1 + l * MLPD, nullptr, m1, MTOK, MLPD, DIM);
        sgemm_k<1><<<gproj, 256>>>(m1, W2 + (size_t)l * MLPD * DIM, b2 + l * DIM, h, h, MTOK, DIM, MLPD);
    }

    pool_k<<<(BVAL * DIM + 255) / 256, 256>>>(h, pool);
    head_k<<<BVAL, 256>>>(pool, head_W, out);
}

// round 5
// speedup vs baseline: 1.2369x; 1.2369x over previous
#include <cuda_runtime.h>
#include <cuda_bf16.h>
#include <math.h>
#include <stdint.h>
#include <cstdint>

// ---------------- problem constants ----------------
#define BVAL 32
#define CCH 3
#define HH 224
#define WW 224
#define PS 16
#define DIM 768
#define NHEAD 12
#define HDIM 64
#define DEPTH 12
#define MLPD 3072
#define NCLS 1000
#define GH_ 14
#define GW_ 14
#define TT 196
#define PD 768               // patch dim = 16*16*3
#define MTOK (BVAL*TT)       // 6272 token rows

// ---------------- scratch (device globals; no runtime alloc allowed) ----------------
__device__ float g_P  [MTOK*PD];
__device__ float g_h  [MTOK*DIM];
__device__ float g_xn [MTOK*DIM];
__device__ float g_q  [MTOK*DIM];
__device__ float g_k  [MTOK*DIM];
__device__ float g_v  [MTOK*DIM];
__device__ float g_att[MTOK*DIM];
__device__ float g_S  [BVAL*NHEAD*TT*TT];
__device__ float g_m1 [(size_t)MTOK*MLPD];
__device__ float g_pos[TT*DIM];
__device__ float g_Wq [DEPTH*DIM*DIM];
__device__ float g_Wk [DEPTH*DIM*DIM];
__device__ float g_Wv [DEPTH*DIM*DIM];
__device__ float g_pool[BVAL*DIM];

// ---------------- small kernels ----------------

__global__ void patchify_k(const float* __restrict__ x, float* __restrict__ P) {
    int idx = blockIdx.x * blockDim.x + threadIdx.x;
    if (idx >= MTOK * PD) return;
    int bt = idx / PD, pc = idx % PD;
    int c = pc % 3, p2 = (pc / 3) % 16, p1 = pc / 48;
    int b = bt / TT, t = bt % TT;
    int gh = t / GW_, gw = t % GW_;
    P[idx] = x[((b * CCH + c) * HH + gh * PS + p1) * WW + gw * PS + p2];
}

__global__ void pack_qkv_k(const float* __restrict__ W, float* __restrict__ out) {
    int idx = blockIdx.x * blockDim.x + threadIdx.x;
    if (idx >= DEPTH * DIM * DIM) return;
    int l = idx / (DIM * DIM);
    int r = idx % (DIM * DIM);
    int d = r / DIM, n = r % DIM;
    int h = n / HDIM, e = n % HDIM;
    out[idx] = W[((l * NHEAD + h) * DIM + d) * HDIM + e];
}

__global__ void pos_k(float* __restrict__ pos) {
    int idx = blockIdx.x * blockDim.x + threadIdx.x;
    if (idx >= TT * DIM) return;
    int t = idx / DIM, d = idx % DIM;
    int q = d / 192, j = d % 192;
    float omega = powf(10000.0f, -(float)j / 191.0f);
    float yv = (float)(t / GW_) * omega;
    float xv = (float)(t % GW_) * omega;
    float v = (q == 0) ? sinf(xv) : (q == 1) ? cosf(xv) : (q == 2) ? sinf(yv) : cosf(yv);
    pos[idx] = v;
}

__global__ void addpos_k(float* __restrict__ h, const float* __restrict__ pos) {
    int idx = blockIdx.x * blockDim.x + threadIdx.x;
    if (idx >= MTOK * DIM) return;
    int bt = idx / DIM, d = idx % DIM;
    int t = bt % TT;
    h[idx] += pos[t * DIM + d];
}

// LayerNorm over D=768; one block (256 thr) per row
__global__ void ln_k(const float* __restrict__ X, const float* __restrict__ g,
                     const float* __restrict__ b, float* __restrict__ Y) {
    int row = blockIdx.x;
    int tid = threadIdx.x;
    const float* xr = X + (size_t)row * DIM;
    float v[3], s = 0.f, s2 = 0.f;
#pragma unroll
    for (int i = 0; i < 3; i++) {
        v[i] = xr[tid + i * 256];
        s += v[i];
        s2 += v[i] * v[i];
    }
#pragma unroll
    for (int o = 16; o; o >>= 1) {
        s  += __shfl_xor_sync(0xffffffffu, s,  o);
        s2 += __shfl_xor_sync(0xffffffffu, s2, o);
    }
    __shared__ float sm[8], sm2[8];
    __shared__ float mu_s, rstd_s;
    int w = tid >> 5, lane = tid & 31;
    if (!lane) { sm[w] = s; sm2[w] = s2; }
    __syncthreads();
    if (tid == 0) {
        float a = 0.f, a2 = 0.f;
        for (int i = 0; i < 8; i++) { a += sm[i]; a2 += sm2[i]; }
        float mu = a / 768.0f;
        float var = a2 / 768.0f - mu * mu;
        mu_s = mu;
        rstd_s = rsqrtf(var + 1e-5f);
    }
    __syncthreads();
    float mu = mu_s, rstd = rstd_s;
#pragma unroll
    for (int i = 0; i < 3; i++) {
        int d = tid + i * 256;
        Y[(size_t)row * DIM + d] = (v[i] - mu) * rstd * g[d] + b[d];
    }
}

// ---------------- bf16x3 split tensor-core GEMM ----------------
// C[M,N] = A[M,K] @ B[K,N] with near-fp32 accuracy via 3-term bf16 split.
// Tiles: 128x128x16, 8 warps of 64x32, mma.sync m16n8k16 bf16 (3 mma per tile).
// EPI 0: C = acc (+bias)   EPI 1: C = acc + bias + R   EPI 2: C = gelu(acc + bias)
// Requires M%128==0, N%128==0, K%16==0.

__device__ __forceinline__ void bsplit(float x, __nv_bfloat16& h, __nv_bfloat16& l) {
    h = __float2bfloat16_rn(x);
    l = __float2bfloat16_rn(x - __bfloat162float(h));
}
__device__ __forceinline__ uint32_t pack2(__nv_bfloat16 a, __nv_bfloat16 b) {
    __nv_bfloat162 t; t.x = a; t.y = b;
    return *(uint32_t*)&t;
}

#define MMA_BF16(d, a, b) asm volatile( \
    "mma.sync.aligned.m16n8k16.row.col.f32.bf16.bf16.f32 " \
    "{%0,%1,%2,%3}, {%4,%5,%6,%7}, {%8,%9}, {%0,%1,%2,%3};\n" \
    : "+f"(d[0]), "+f"(d[1]), "+f"(d[2]), "+f"(d[3]) \
    : "r"(a[0]), "r"(a[1]), "r"(a[2]), "r"(a[3]), "r"(b[0]), "r"(b[1]))

template <int EPI>
__global__ void __launch_bounds__(256, 2)
mma_gemm_k(const float* __restrict__ A, const float* __restrict__ B,
           const float* __restrict__ bias, const float* __restrict__ R,
           float* __restrict__ C, int M, int N, int K) {
    // A planes: [row 0..127][k 0..15] bf16, row stride 24 halves
    __shared__ __align__(16) __nv_bfloat16 AsH[2][128][24];
    __shared__ __align__(16) __nv_bfloat16 AsL[2][128][24];
    // B planes: packed k-pairs: [kpair 0..7][n 0..127] uint32, row stride 136
    __shared__ __align__(16) uint32_t BsH[2][8][136];
    __shared__ __align__(16) uint32_t BsL[2][8][136];

    int tid = threadIdx.x;
    int lane = tid & 31, warp = tid >> 5;
    int wm = warp >> 2, wn = warp & 3;
    int q = lane & 3, r4 = lane >> 2;

    const float* Ab = A + (size_t)blockIdx.y * 128 * K;
    const float* Bb = B + (size_t)blockIdx.x * 128;

    int ar = tid >> 1, ah = (tid & 1) * 8;       // A staging: row, k-half
    int kp = tid >> 5, n4 = (tid & 31) * 4;      // B staging: k-pair, n quad

    float acc[4][4][4];
#pragma unroll
    for (int mt = 0; mt < 4; mt++)
#pragma unroll
        for (int nt = 0; nt < 4; nt++)
#pragma unroll
            for (int i = 0; i < 4; i++) acc[mt][nt][i] = 0.f;

    float4 aR0, aR1, bR0, bR1;
    auto load_g = [&](int k0) {
        aR0 = *(const float4*)(Ab + (size_t)ar * K + k0 + ah);
        aR1 = *(const float4*)(Ab + (size_t)ar * K + k0 + ah + 4);
        bR0 = *(const float4*)(Bb + (size_t)(k0 + 2 * kp) * N + n4);
        bR1 = *(const float4*)(Bb + (size_t)(k0 + 2 * kp + 1) * N + n4);
    };
    auto store_s = [&](int buf) {
        float av[8] = {aR0.x, aR0.y, aR0.z, aR0.w, aR1.x, aR1.y, aR1.z, aR1.w};
        __nv_bfloat16 hh[8], ll[8];
#pragma unroll
        for (int i = 0; i < 8; i++) bsplit(av[i], hh[i], ll[i]);
        *(uint4*)&AsH[buf][ar][ah] = *(uint4*)hh;
        *(uint4*)&AsL[buf][ar][ah] = *(uint4*)ll;
        float b0v[4] = {bR0.x, bR0.y, bR0.z, bR0.w};
        float b1v[4] = {bR1.x, bR1.y, bR1.z, bR1.w};
        uint32_t ph[4], pl[4];
#pragma unroll
        for (int j = 0; j < 4; j++) {
            __nv_bfloat16 h0, l0, h1, l1;
            bsplit(b0v[j], h0, l0);
            bsplit(b1v[j], h1, l1);
            ph[j] = pack2(h0, h1);
            pl[j] = pack2(l0, l1);
        }
        *(uint4*)&BsH[buf][kp][n4] = *(uint4*)ph;
        *(uint4*)&BsL[buf][kp][n4] = *(uint4*)pl;
    };

    load_g(0);
    store_s(0);
    __syncthreads();

    int buf = 0;
    int niter = K / 16;
    for (int it = 0; it < niter; ++it) {
        if (it + 1 < niter) load_g((it + 1) * 16);

        uint32_t bh[4][2], bl[4][2];
#pragma unroll
        for (int nt = 0; nt < 4; nt++) {
            int n0 = wn * 32 + nt * 8 + r4;
            bh[nt][0] = BsH[buf][q][n0];
            bh[nt][1] = BsH[buf][q + 4][n0];
            bl[nt][0] = BsL[buf][q][n0];
            bl[nt][1] = BsL[buf][q + 4][n0];
        }
#pragma unroll
        for (int mt = 0; mt < 4; mt++) {
            int m0 = wm * 64 + mt * 16 + r4;
            uint32_t ahf[4], alf[4];
            ahf[0] = *(const uint32_t*)&AsH[buf][m0][2 * q];
            ahf[1] = *(const uint32_t*)&AsH[buf][m0 + 8][2 * q];
            ahf[2] = *(const uint32_t*)&AsH[buf][m0][2 * q + 8];
            ahf[3] = *(const uint32_t*)&AsH[buf][m0 + 8][2 * q + 8];
            alf[0] = *(const uint32_t*)&AsL[buf][m0][2 * q];
            alf[1] = *(const uint32_t*)&AsL[buf][m0 + 8][2 * q];
            alf[2] = *(const uint32_t*)&AsL[buf][m0][2 * q + 8];
            alf[3] = *(const uint32_t*)&AsL[buf][m0 + 8][2 * q + 8];
#pragma unroll
            for (int nt = 0; nt < 4; nt++) {
                MMA_BF16(acc[mt][nt], ahf, bh[nt]);
                MMA_BF16(acc[mt][nt], ahf, bl[nt]);
                MMA_BF16(acc[mt][nt], alf, bh[nt]);
            }
        }
        if (it + 1 < niter) store_s(buf ^ 1);
        __syncthreads();
        buf ^= 1;
    }

    // epilogue: each thread owns, per (mt,nt), rows {r4, r4+8}, cols {2q, 2q+1}
#pragma unroll
    for (int mt = 0; mt < 4; mt++) {
#pragma unroll
        for (int nt = 0; nt < 4; nt++) {
            int col = blockIdx.x * 128 + wn * 32 + nt * 8 + 2 * q;
            float bias0 = bias ? bias[col] : 0.f;
            float bias1 = bias ? bias[col + 1] : 0.f;
#pragma unroll
            for (int half = 0; half < 2; half++) {
                int row = blockIdx.y * 128 + wm * 64 + mt * 16 + r4 + half * 8;
                float v0 = acc[mt][nt][half * 2 + 0] + bias0;
                float v1 = acc[mt][nt][half * 2 + 1] + bias1;
                if (EPI == 1) {
                    const float2 rr = *(const float2*)(R + (size_t)row * N + col);
                    v0 += rr.x; v1 += rr.y;
                }
                if (EPI == 2) {
                    v0 = 0.5f * v0 * (1.0f + erff(v0 * 0.70710678118654752f));
                    v1 = 0.5f * v1 * (1.0f + erff(v1 * 0.70710678118654752f));
                }
                float2 o; o.x = v0; o.y = v1;
                *(float2*)(C + (size_t)row * N + col) = o;
            }
        }
    }
}

// ---------------- attention ----------------
__global__ void attn_scores_k(const float* __restrict__ Q, const float* __restrict__ K,
                              float* __restrict__ S) {
    int bh = blockIdx.x;
    int t = blockIdx.y;
    int b = bh / NHEAD, h = bh % NHEAD;
    int tid = threadIdx.x;
    int w = tid >> 5, lane = tid & 31;

    __shared__ float qsh[HDIM];
    __shared__ float sred[7];
    __shared__ float sbro;

    if (tid < HDIM) qsh[tid] = Q[(size_t)(b * TT + t) * DIM + h * HDIM + tid];
    __syncthreads();

    int s = tid;
    float val = -INFINITY;
    if (s < TT) {
        const float* kr = K + (size_t)(b * TT + s) * DIM + h * HDIM;
        float dot = 0.f;
#pragma unroll
        for (int d = 0; d < HDIM; d++) dot += qsh[d] * kr[d];
        val = dot * 0.125f;
    }
    float m = val;
#pragma unroll
    for (int o = 16; o; o >>= 1) m = fmaxf(m, __shfl_xor_sync(0xffffffffu, m, o));
    if (!lane) sred[w] = m;
    __syncthreads();
    if (tid == 0) {
        float mm = sred[0];
        for (int i = 1; i < 7; i++) mm = fmaxf(mm, sred[i]);
        sbro = mm;
    }
    __syncthreads();
    float rowmax = sbro;
    float e = (s < TT) ? expf(val - rowmax) : 0.f;
    float su = e;
#pragma unroll
    for (int o = 16; o; o >>= 1) su += __shfl_xor_sync(0xffffffffu, su, o);
    __syncthreads();
    if (!lane) sred[w] = su;
    __syncthreads();
    if (tid == 0) {
        float ss = 0.f;
        for (int i = 0; i < 7; i++) ss += sred[i];
        sbro = 1.0f / ss;
    }
    __syncthreads();
    if (s < TT) S[((size_t)bh * TT + t) * TT + s] = e * sbro;
}

__global__ void attn_av_k(const float* __restrict__ S, const float* __restrict__ V,
                          float* __restrict__ O) {
    int bh = blockIdx.x, t = blockIdx.y;
    int b = bh / NHEAD, h = bh % NHEAD;
    int tid = threadIdx.x;
    __shared__ float psh[TT];
    for (int s = tid; s < TT; s += 64) psh[s] = S[((size_t)bh * TT + t) * TT + s];
    __syncthreads();
    float acc = 0.f;
    const float* vb = V + (size_t)b * TT * DIM + h * HDIM + tid;
#pragma unroll 4
    for (int s = 0; s < TT; s++) acc += psh[s] * vb[(size_t)s * DIM];
    O[(size_t)(b * TT + t) * DIM + h * HDIM + tid] = acc;
}

// ---------------- pool + head ----------------
__global__ void pool_k(const float* __restrict__ h, float* __restrict__ pool) {
    int idx = blockIdx.x * blockDim.x + threadIdx.x;
    if (idx >= BVAL * DIM) return;
    int b = idx / DIM, d = idx % DIM;
    float s = 0.f;
    const float* hp = h + (size_t)b * TT * DIM + d;
    for (int t = 0; t < TT; t++) s += hp[(size_t)t * DIM];
    pool[idx] = s * (1.0f / 196.0f);
}

__global__ void head_k(const float* __restrict__ pool, const float* __restrict__ W,
                       float* __restrict__ out) {
    int b = blockIdx.x;
    int tid = threadIdx.x;
    __shared__ float pr[DIM];
    for (int i = tid; i < DIM; i += 256) pr[i] = pool[b * DIM + i];
    __syncthreads();
    for (int n = tid; n < NCLS; n += 256) {
        float acc = 0.f;
        for (int k = 0; k < DIM; k++) acc += pr[k] * W[(size_t)k * NCLS + n];
        out[b * NCLS + n] = acc;
    }
}

// ---------------- launch ----------------
extern "C" void kernel_launch(void* const* d_in, const int* in_sizes, int n_in,
                              void* d_out, int out_size) {
    const float* x       = (const float*)d_in[0];
    const float* embed_W = (const float*)d_in[1];
    const float* embed_b = (const float*)d_in[2];
    const float* Wq      = (const float*)d_in[3];
    const float* Wk      = (const float*)d_in[4];
    const float* Wv      = (const float*)d_in[5];
    const float* Wo      = (const float*)d_in[6];
    const float* bo      = (const float*)d_in[7];
    const float* ln1_g   = (const float*)d_in[8];
    const float* ln1_b   = (const float*)d_in[9];
    const float* ln2_g   = (const float*)d_in[10];
    const float* ln2_b   = (const float*)d_in[11];
    const float* W1      = (const float*)d_in[12];
    const float* b1      = (const float*)d_in[13];
    const float* W2      = (const float*)d_in[14];
    const float* b2      = (const float*)d_in[15];
    const float* head_W  = (const float*)d_in[16];
    float* out = (float*)d_out;

    float *P, *h, *xn, *q, *k, *v, *att, *S, *m1, *pos, *wqp, *wkp, *wvp, *pool;
    cudaGetSymbolAddress((void**)&P,   g_P);
    cudaGetSymbolAddress((void**)&h,   g_h);
    cudaGetSymbolAddress((void**)&xn,  g_xn);
    cudaGetSymbolAddress((void**)&q,   g_q);
    cudaGetSymbolAddress((void**)&k,   g_k);
    cudaGetSymbolAddress((void**)&v,   g_v);
    cudaGetSymbolAddress((void**)&att, g_att);
    cudaGetSymbolAddress((void**)&S,   g_S);
    cudaGetSymbolAddress((void**)&m1,  g_m1);
    cudaGetSymbolAddress((void**)&pos, g_pos);
    cudaGetSymbolAddress((void**)&wqp, g_Wq);
    cudaGetSymbolAddress((void**)&wkp, g_Wk);
    cudaGetSymbolAddress((void**)&wvp, g_Wv);
    cudaGetSymbolAddress((void**)&pool, g_pool);

    // first 5 launches are prep; 6th launch (embed GEMM) is what ncu -s 5 -c 1 captures
    pack_qkv_k<<<(DEPTH * DIM * DIM + 255) / 256, 256>>>(Wq, wqp);
    pack_qkv_k<<<(DEPTH * DIM * DIM + 255) / 256, 256>>>(Wk, wkp);
    pack_qkv_k<<<(DEPTH * DIM * DIM + 255) / 256, 256>>>(Wv, wvp);
    patchify_k<<<(MTOK * PD + 255) / 256, 256>>>(x, P);
    pos_k<<<(TT * DIM + 255) / 256, 256>>>(pos);

    mma_gemm_k<0><<<dim3(DIM / 128, MTOK / 128), 256>>>(P, embed_W, embed_b, nullptr, h,
                                                        MTOK, DIM, PD);
    addpos_k<<<(MTOK * DIM + 255) / 256, 256>>>(h, pos);

    dim3 gproj(DIM / 128, MTOK / 128);     // 6 x 49
    dim3 gmlp1(MLPD / 128, MTOK / 128);    // 24 x 49
    dim3 gattn(BVAL * NHEAD, TT);          // 384 x 196

    for (int l = 0; l < DEPTH; l++) {
        ln_k<<<MTOK, 256>>>(h, ln1_g + l * DIM, ln1_b + l * DIM, xn);
        mma_gemm_k<0><<<gproj, 256>>>(xn, wqp + (size_t)l * DIM * DIM, nullptr, nullptr, q, MTOK, DIM, DIM);
        mma_gemm_k<0><<<gproj, 256>>>(xn, wkp + (size_t)l * DIM * DIM, nullptr, nullptr, k, MTOK, DIM, DIM);
        mma_gemm_k<0><<<gproj, 256>>>(xn, wvp + (size_t)l * DIM * DIM, nullptr, nullptr, v, MTOK, DIM, DIM);
        attn_scores_k<<<gattn, 224>>>(q, k, S);
        attn_av_k<<<gattn, 64>>>(S, v, att);
        mma_gemm_k<1><<<gproj, 256>>>(att, Wo + (size_t)l * DIM * DIM, bo + l * DIM, h, h, MTOK, DIM, DIM);
        ln_k<<<MTOK, 256>>>(h, ln2_g + l * DIM, ln2_b + l * DIM, xn);
        mma_gemm_k<2><<<gmlp1, 256>>>(xn, W1 + (size_t)l * DIM * MLPD, b1 + l * MLPD, nullptr, m1, MTOK, MLPD, DIM);
        mma_gemm_k<1><<<gproj, 256>>>(m1, W2 + (size_t)l * MLPD * DIM, b2 + l * DIM, h, h, MTOK, DIM, MLPD);
    }

    pool_k<<<(BVAL * DIM + 255) / 256, 256>>>(h, pool);
    head_k<<<BVAL, 256>>>(pool, head_W, out);
}